// round 3
// baseline (speedup 1.0000x reference)
#include <cuda_runtime.h>
#include <math.h>

// Problem constants
#define NBAS 1024   // basis functions
#define LM   512    // memory length actually used
#define HH   16
#define DD   128
#define QL   2048
#define DM   2048   // model dim = H*D

// ---------------- scratch (static __device__, no allocs) ----------------
__device__ double g_A[NBAS * NBAS];      // banded A -> Cholesky L (lower), fp64
__device__ double g_Frhs[NBAS * LM];     // RHS = F middle 512 columns (fp64)
__device__ double g_Yd[NBAS * LM];       // forward-solve intermediate
__device__ float  g_X[NBAS * LM];        // X = A^{-1} F_mid  (fp32)  [n][l]
__device__ float  g_B[NBAS * DM];        // B[n][d]
__device__ float  g_V[NBAS * DM];        // values [n][h*128+dd]
__device__ float  g_ctx[QL * DM];        // context [q][h*128+dd]
__device__ float  g_bw[2 * DM];          // bwmu, bwsig
__device__ float  g_kv[2 * DM];          // kmu, ksig
__device__ float  g_mu[HH * QL];
__device__ float  g_s2[HH * QL];

// ---------------- helpers ----------------
__device__ __forceinline__ float wredf(float v) {
    #pragma unroll
    for (int o = 16; o; o >>= 1) v += __shfl_xor_sync(0xffffffffu, v, o);
    return v;
}
__device__ __forceinline__ double wredd(double v) {
    #pragma unroll
    for (int o = 16; o; o >>= 1) v += __shfl_xor_sync(0xffffffffu, v, o);
    return v;
}

// ---------------- 1. A = F F^T + 0.5 I  ANALYTIC, band only ----------------
// A_ij = 512 * exp(-dmu^2/(2 s2)) / sqrt(2 pi s2),  s2 = sig_i^2 + sig_j^2
// (Poisson-summation correction <= e^-64; boundary truncation >= 70 sigma: exact
//  to fp64 noise). Stored lower blocks with block-offset 0..2 only (64-wide).
__global__ void k_buildA() {
    int bj = blockIdx.x, bi = bj + blockIdx.y;
    if (bi >= NBAS / 64) return;
    for (int t = threadIdx.x; t < 4096; t += 256) {
        int li = t >> 6, lj = t & 63;
        int i = bi * 64 + li, j = bj * 64 + lj;
        if (i < j) continue;
        double dmu = (double)((i >> 1) - (j >> 1)) * (1.0 / 511.0);
        double s2 = ((i & 1) ? 1e-4 : 2.5e-5) + ((j & 1) ? 1e-4 : 2.5e-5);
        double v = 512.0 * exp(-0.5 * dmu * dmu / s2) / sqrt(6.283185307179586 * s2);
        if (i == j) v += 0.5;
        g_A[(size_t)i * NBAS + j] = v;
    }
}

// ---------------- 1b. RHS = F[:, 256:768] (the G slice) ----------------
// pos_{256+c} = -0.5 + 1/1024 + (256+c)/512 = 0.0009765625 + c/512
__global__ void k_buildFrhs() {
    int n = blockIdx.x;
    double mu = (double)(n >> 1) / 511.0;
    double sg = (n & 1) ? 0.01 : 0.005;
    double inv = 1.0 / (sg * 2.5066282746310002);
    for (int c = threadIdx.x; c < LM; c += blockDim.x) {
        double pos = 0.0009765625 + (double)c * (1.0 / 512.0);
        double z = (pos - mu) / sg;
        g_Frhs[n * LM + c] = exp(-0.5 * z * z) * inv;
    }
}

// ---------------- 2a. Cholesky diagonal block (64x64, fp64) ----------------
__global__ void k_chol_diag(int k0) {
    __shared__ double s[64][64];
    int tid = threadIdx.x;
    for (int t = tid; t < 4096; t += 256) {
        int i = t >> 6, j = t & 63;
        s[i][j] = (i >= j) ? g_A[(size_t)(k0 + i) * NBAS + k0 + j] : 0.0;
    }
    __syncthreads();
    for (int j = 0; j < 64; j++) {
        if (tid == 0) s[j][j] = sqrt(s[j][j]);
        __syncthreads();
        double inv = 1.0 / s[j][j];
        for (int i = j + 1 + tid; i < 64; i += 256) s[i][j] *= inv;
        __syncthreads();
        for (int t = tid; t < 4096; t += 256) {
            int i = t >> 6, c = t & 63;
            if (c > j && c <= i) s[i][c] -= s[i][j] * s[c][j];
        }
        __syncthreads();
    }
    for (int t = tid; t < 4096; t += 256) {
        int i = t >> 6, j = t & 63;
        if (i >= j) g_A[(size_t)(k0 + i) * NBAS + k0 + j] = s[i][j];
    }
}

// ---------------- 2b. panel: L21 = A21 * L11^{-T}, rows k0+64 .. k0+191 ----------------
__global__ void k_chol_panel(int k0) {
    __shared__ double Ld[64][64];
    int tid = threadIdx.x;
    for (int t = tid; t < 4096; t += 256) {
        int i = t >> 6, j = t & 63;
        Ld[i][j] = (i >= j) ? g_A[(size_t)(k0 + i) * NBAS + k0 + j] : 0.0;
    }
    __syncthreads();
    int lane = tid & 31, w = tid >> 5;
    int row = k0 + 64 + blockIdx.x * 8 + w;
    if (row >= NBAS) return;
    double a0 = g_A[(size_t)row * NBAS + k0 + lane];
    double a1 = g_A[(size_t)row * NBAS + k0 + 32 + lane];
    for (int j = 0; j < 64; j++) {
        double p = 0.0;
        if (lane < j)       p += a0 * Ld[j][lane];
        if (lane + 32 < j)  p += a1 * Ld[j][lane + 32];
        p = wredd(p);
        double av = (j < 32) ? __shfl_sync(0xffffffffu, a0, j)
                             : __shfl_sync(0xffffffffu, a1, j - 32);
        double xj = (av - p) / Ld[j][j];
        if (j < 32) { if (lane == j) a0 = xj; }
        else        { if (lane == j - 32) a1 = xj; }
    }
    g_A[(size_t)row * NBAS + k0 + lane] = a0;
    g_A[(size_t)row * NBAS + k0 + 32 + lane] = a1;
}

// ---------------- 2c. trailing update: 3 block pairs, 8-row strips ----------------
// pairs (dbi,dbj): 0->(0,0), 1->(1,0), 2->(1,1); relative to b0 = k0/64+1
__global__ void k_trail(int k0) {
    int pair = blockIdx.x >> 3, strip = blockIdx.x & 7;
    int dbi = (pair >= 1) ? 1 : 0, dbj = (pair == 2) ? 1 : 0;
    int i0 = k0 + 64 + dbi * 64 + strip * 8;
    int j0 = k0 + 64 + dbj * 64;
    if (i0 >= NBAS || j0 >= NBAS) return;
    __shared__ double Lj[64][65];
    __shared__ double Li[8][65];
    int tid = threadIdx.x;
    for (int t = tid; t < 4096; t += 256)
        Lj[t >> 6][t & 63] = g_A[(size_t)(j0 + (t >> 6)) * NBAS + k0 + (t & 63)];
    for (int t = tid; t < 512; t += 256)
        Li[t >> 6][t & 63] = g_A[(size_t)(i0 + (t >> 6)) * NBAS + k0 + (t & 63)];
    __syncthreads();
    // 8 x 64 outputs, 2 per thread: (r, c) and (r+4, c)
    int r = tid >> 6, c = tid & 63;
    double acc0 = 0.0, acc1 = 0.0;
    #pragma unroll 8
    for (int k = 0; k < 64; k++) {
        double lj = Lj[c][k];
        acc0 += Li[r][k] * lj;
        acc1 += Li[r + 4][k] * lj;
    }
    g_A[(size_t)(i0 + r) * NBAS + j0 + c]     -= acc0;
    g_A[(size_t)(i0 + r + 4) * NBAS + j0 + c] -= acc1;
}

// ---------------- 3. forward solve L Y = F_mid (band, warp per 4 cols) ----------------
__global__ void __launch_bounds__(32) k_trsm_fwd() {
    __shared__ double ys[4][NBAS];
    int lane = threadIdx.x;
    int col0 = blockIdx.x * 4;
    for (int n = 0; n < NBAS; n++) {
        int jlo = ((n >> 6) >= 2) ? (((n >> 6) - 2) << 6) : 0;
        double a0 = 0, a1 = 0, a2 = 0, a3 = 0;
        const double* Ln = &g_A[(size_t)n * NBAS];
        for (int j = jlo + lane; j < n; j += 32) {
            double L = Ln[j];
            a0 += L * ys[0][j]; a1 += L * ys[1][j];
            a2 += L * ys[2][j]; a3 += L * ys[3][j];
        }
        a0 = wredd(a0); a1 = wredd(a1); a2 = wredd(a2); a3 = wredd(a3);
        double dinv = 1.0 / Ln[n];
        if (lane < 4) {
            double acc = (lane == 0) ? a0 : (lane == 1) ? a1 : (lane == 2) ? a2 : a3;
            double c = g_Frhs[n * LM + col0 + lane];
            double y = (c - acc) * dinv;
            ys[lane][n] = y;
            g_Yd[n * LM + col0 + lane] = y;
        }
        __syncwarp();
    }
}

// ---------------- 4. backward solve L^T X = Y (band) ----------------
__global__ void __launch_bounds__(32) k_trsm_bwd() {
    __shared__ double xs[4][NBAS];
    int lane = threadIdx.x;
    int col0 = blockIdx.x * 4;
    for (int n = NBAS - 1; n >= 0; n--) {
        int jhi = (((n >> 6) + 3) << 6); if (jhi > NBAS) jhi = NBAS;
        double a0 = 0, a1 = 0, a2 = 0, a3 = 0;
        for (int j = n + 1 + lane; j < jhi; j += 32) {
            double L = g_A[(size_t)j * NBAS + n];
            a0 += L * xs[0][j]; a1 += L * xs[1][j];
            a2 += L * xs[2][j]; a3 += L * xs[3][j];
        }
        a0 = wredd(a0); a1 = wredd(a1); a2 = wredd(a2); a3 = wredd(a3);
        double dinv = 1.0 / g_A[(size_t)n * NBAS + n];
        if (lane < 4) {
            double acc = (lane == 0) ? a0 : (lane == 1) ? a1 : (lane == 2) ? a2 : a3;
            double y = g_Yd[n * LM + col0 + lane];
            double x = (y - acc) * dinv;
            xs[lane][n] = x;
            g_X[n * LM + col0 + lane] = (float)x;
        }
        __syncwarp();
    }
}

// ---------------- generic 128x128x8 SGEMM, C = A * op(B) ----------------
// NT=true : B is [N][K] row-major (C = A B^T), NT=false: B is [K][N] row-major
template <bool NT>
__global__ void __launch_bounds__(256) k_gemm128(const float* __restrict__ Am,
                                                 const float* __restrict__ Bm,
                                                 float* __restrict__ C,
                                                 int M, int Nn, int K) {
    __shared__ float As[8][132];
    __shared__ float Bs[8][132];
    int tx = threadIdx.x & 15, ty = threadIdx.x >> 4;
    int m0 = blockIdx.y * 128, n0 = blockIdx.x * 128;
    float acc[8][8] = {};
    for (int k0 = 0; k0 < K; k0 += 8) {
        {
            int r = threadIdx.x >> 1, c = (threadIdx.x & 1) * 4;
            float4 v = *(const float4*)&Am[(size_t)(m0 + r) * K + k0 + c];
            As[c + 0][r] = v.x; As[c + 1][r] = v.y; As[c + 2][r] = v.z; As[c + 3][r] = v.w;
        }
        if (NT) {
            int r = threadIdx.x >> 1, c = (threadIdx.x & 1) * 4;
            float4 v = *(const float4*)&Bm[(size_t)(n0 + r) * K + k0 + c];
            Bs[c + 0][r] = v.x; Bs[c + 1][r] = v.y; Bs[c + 2][r] = v.z; Bs[c + 3][r] = v.w;
        } else {
            int r = threadIdx.x >> 5, c = (threadIdx.x & 31) * 4;
            float4 v = *(const float4*)&Bm[(size_t)(k0 + r) * Nn + n0 + c];
            *(float4*)&Bs[r][c] = v;
        }
        __syncthreads();
        #pragma unroll
        for (int kk = 0; kk < 8; kk++) {
            float a[8], b[8];
            *(float4*)&a[0] = *(float4*)&As[kk][ty * 8];
            *(float4*)&a[4] = *(float4*)&As[kk][ty * 8 + 4];
            *(float4*)&b[0] = *(float4*)&Bs[kk][tx * 8];
            *(float4*)&b[4] = *(float4*)&Bs[kk][tx * 8 + 4];
            #pragma unroll
            for (int i = 0; i < 8; i++)
                #pragma unroll
                for (int j = 0; j < 8; j++) acc[i][j] += a[i] * b[j];
        }
        __syncthreads();
    }
    #pragma unroll
    for (int i = 0; i < 8; i++)
        #pragma unroll
        for (int j = 0; j < 8; j++)
            C[(size_t)(m0 + ty * 8 + i) * Nn + n0 + tx * 8 + j] = acc[i][j];
}

// ---------------- 6. bwmu/bwsig = B^T w ----------------
__global__ void k_bw(const float* __restrict__ wmu, const float* __restrict__ wsig) {
    int d = blockIdx.x * 256 + threadIdx.x;
    float am = 0.f, as = 0.f;
    for (int n = 0; n < NBAS; n++) {
        float b = g_B[n * DM + d];
        am += wmu[n] * b;
        as += wsig[n] * b;
    }
    g_bw[d] = am;
    g_bw[DM + d] = as;
}

// ---------------- 7. kmu/ksig = W_key * bw ----------------
__global__ void k_kmat(const float* __restrict__ Wkey) {
    int lane = threadIdx.x & 31, w = threadIdx.x >> 5;
    int e = blockIdx.x * 8 + w;
    float am = 0.f, as = 0.f;
    const float* row = Wkey + (size_t)e * DM;
    for (int d = lane; d < DM; d += 32) {
        float wv = row[d];
        am += wv * g_bw[d];
        as += wv * g_bw[DM + d];
    }
    am = wredf(am); as = wredf(as);
    if (lane == 0) { g_kv[e] = am; g_kv[DM + e] = as; }
}

// ---------------- 8. mu_s / sigma_sq per (h,q) ----------------
__global__ void k_musig(const float* __restrict__ q) {
    int lane = threadIdx.x & 31, w = threadIdx.x >> 5;
    int row = blockIdx.x * 8 + w;          // h*QL + qq
    int h = row >> 11;
    const float* qp = q + (size_t)row * DD;
    float am = 0.f, as = 0.f;
    for (int dd = lane; dd < DD; dd += 32) {
        float v = qp[dd];
        am += v * g_kv[h * DD + dd];
        as += v * g_kv[DM + h * DD + dd];
    }
    am = wredf(am); as = wredf(as);
    if (lane == 0) {
        const float isq = 0.08838834764831845f;  // 1/sqrt(128)
        float xm = am * isq;
        float xs = as * isq;
        g_mu[row] = 1.0f / (1.0f + expf(-xm));
        float sp = fmaxf(xs, 0.f) + log1pf(expf(-fabsf(xs)));
        g_s2[row] = fmaxf(sp, 1e-4f);
    }
}

// ---------------- 9. fused r + context GEMM ----------------
// context[q][h*128+dd] = sum_n r(h,q,n) * V[n][h*128+dd]
__global__ void __launch_bounds__(256) k_context() {
    int h = blockIdx.y;
    int q0 = blockIdx.x * 64;
    __shared__ float rs[16][68];
    __shared__ float Vs[16][132];
    __shared__ float sm[64], sv[64];
    int tid = threadIdx.x, tx = tid & 15, ty = tid >> 4;
    if (tid < 64) {
        sm[tid] = g_mu[h * QL + q0 + tid];
        sv[tid] = g_s2[h * QL + q0 + tid];
    }
    __syncthreads();
    float acc[4][8] = {};
    for (int n0 = 0; n0 < NBAS; n0 += 16) {
        {
            int r = tid >> 4, c = (tid & 15) * 8;
            const float* src = &g_V[(size_t)(n0 + r) * DM + h * DD + c];
            *(float4*)&Vs[r][c]     = *(const float4*)&src[0];
            *(float4*)&Vs[r][c + 4] = *(const float4*)&src[4];
        }
        for (int t = tid; t < 1024; t += 256) {
            int nq = t & 63;
            int nn = t >> 6;
            int n = n0 + nn;
            float bmu = (float)(n >> 1) * (1.0f / 511.0f);
            float bs2 = (n & 1) ? 1e-4f : 2.5e-5f;
            float tt = sv[nq] + bs2;
            float rt = rsqrtf(tt);
            float df = bmu - sm[nq];
            rs[nn][nq] = __expf(-0.5f * df * df * rt * rt) * rt * 0.3989422804014327f;
        }
        __syncthreads();
        #pragma unroll
        for (int kk = 0; kk < 16; kk++) {
            float a[4], b[8];
            *(float4*)&a[0] = *(float4*)&rs[kk][ty * 4];
            *(float4*)&b[0] = *(float4*)&Vs[kk][tx * 8];
            *(float4*)&b[4] = *(float4*)&Vs[kk][tx * 8 + 4];
            #pragma unroll
            for (int i = 0; i < 4; i++)
                #pragma unroll
                for (int j = 0; j < 8; j++) acc[i][j] += a[i] * b[j];
        }
        __syncthreads();
    }
    #pragma unroll
    for (int i = 0; i < 4; i++)
        #pragma unroll
        for (int j = 0; j < 8; j++)
            g_ctx[(size_t)(q0 + ty * 4 + i) * DM + h * DD + tx * 8 + j] = acc[i][j];
}

// ---------------- host launcher ----------------
extern "C" void kernel_launch(void* const* d_in, const int* in_sizes, int n_in,
                              void* d_out, int out_size) {
    const float* k_in  = (const float*)d_in[0];   // (1, 512, 2048)
    const float* q_in  = (const float*)d_in[1];   // (1, 16, 2048, 128)
    const float* Wkey  = (const float*)d_in[2];   // (2048, 2048)
    const float* Wval  = (const float*)d_in[3];
    const float* Wout  = (const float*)d_in[4];
    const float* wmu   = (const float*)d_in[5];   // (1024,)
    const float* wsig  = (const float*)d_in[6];
    (void)n_in; (void)in_sizes; (void)out_size;

    float *pX, *pB, *pV, *pCtx;
    cudaGetSymbolAddress((void**)&pX,   g_X);
    cudaGetSymbolAddress((void**)&pB,   g_B);
    cudaGetSymbolAddress((void**)&pV,   g_V);
    cudaGetSymbolAddress((void**)&pCtx, g_ctx);

    // 1: analytic banded A and RHS
    k_buildA<<<dim3(16, 3), 256>>>();
    k_buildFrhs<<<NBAS, 256>>>();

    // 2: banded blocked Cholesky (fp64), block-band offset <= 2
    for (int k0 = 0; k0 < NBAS; k0 += 64) {
        k_chol_diag<<<1, 256>>>(k0);
        int rows = NBAS - k0 - 64;
        if (rows > 128) rows = 128;
        if (rows > 0) {
            k_chol_panel<<<rows / 8, 256>>>(k0);
            k_trail<<<24, 256>>>(k0);
        }
    }

    // 3-4: banded triangular solves -> X (fp32)
    k_trsm_fwd<<<128, 32>>>();
    k_trsm_bwd<<<128, 32>>>();

    // 5: B = X * k   (NN: X [1024][512], k [512][2048])
    k_gemm128<false><<<dim3(DM / 128, NBAS / 128), 256>>>(pX, k_in, pB, NBAS, DM, LM);

    // 6-8: collapsed keys/scores path
    k_bw<<<DM / 256, 256>>>(wmu, wsig);
    k_kmat<<<DM / 8, 256>>>(Wkey);
    k_musig<<<(HH * QL) / 8, 256>>>(q_in);

    // 9: values = B * W_val^T (NT)
    k_gemm128<true><<<dim3(DM / 128, NBAS / 128), 256>>>(pB, Wval, pV, NBAS, DM, DM);

    // 10: fused r + context
    k_context<<<dim3(QL / 64, HH), 256>>>();

    // 11: out = ctx * W_out^T (NT) -> d_out
    k_gemm128<true><<<dim3(DM / 128, QL / 128), 256>>>(pCtx, Wout, (float*)d_out, QL, DM, DM);
}

// round 12
// speedup vs baseline: 1.2109x; 1.2109x over previous
#include <cuda_runtime.h>
#include <cuda_bf16.h>
#include <math.h>
#include <stdint.h>

// Problem constants
#define NBAS 1024   // basis functions
#define LM   512    // memory length actually used
#define HH   16
#define DD   128
#define QL   2048
#define DM   2048   // model dim = H*D

// ---------------- scratch (static __device__, no allocs) ----------------
__device__ double g_A[NBAS * NBAS];      // banded A -> Cholesky L (lower), fp64
__device__ double g_Frhs[NBAS * LM];     // RHS = F middle 512 columns (fp64)
__device__ double g_Yd[NBAS * LM];       // forward-solve intermediate
__device__ double g_dinv[NBAS];          // 1 / L[n][n]
__device__ float  g_X[NBAS * LM];        // X = A^{-1} F_mid  (fp32)  [n][l]
__device__ float  g_B[NBAS * DM];        // B[n][d]
__device__ float  g_V[NBAS * DM];        // values [n][h*128+dd]
__device__ float  g_ctx[QL * DM];        // context [q][h*128+dd]
__device__ float  g_bw[2 * DM];          // bwmu, bwsig
__device__ float  g_kv[2 * DM];          // kmu, ksig
__device__ float  g_mu[HH * QL];
__device__ float  g_s2[HH * QL];
// bf16 split operands for tensor-core GEMMs
__device__ __nv_bfloat16 g_Bh[NBAS * DM],  g_Bl[NBAS * DM];
__device__ __nv_bfloat16 g_Wvh[DM * DM],   g_Wvl[DM * DM];
__device__ __nv_bfloat16 g_Woh[DM * DM],   g_Wol[DM * DM];
__device__ __nv_bfloat16 g_Ch[QL * DM],    g_Cl[QL * DM];

// ---------------- helpers ----------------
__device__ __forceinline__ float wredf(float v) {
    #pragma unroll
    for (int o = 16; o; o >>= 1) v += __shfl_xor_sync(0xffffffffu, v, o);
    return v;
}
__device__ __forceinline__ double wredd(double v) {
    #pragma unroll
    for (int o = 16; o; o >>= 1) v += __shfl_xor_sync(0xffffffffu, v, o);
    return v;
}
__device__ __forceinline__ void mma16816(float* c,
    uint32_t a0, uint32_t a1, uint32_t a2, uint32_t a3,
    uint32_t b0, uint32_t b1) {
    asm volatile(
        "mma.sync.aligned.m16n8k16.row.col.f32.bf16.bf16.f32 "
        "{%0,%1,%2,%3}, {%4,%5,%6,%7}, {%8,%9}, {%0,%1,%2,%3};"
        : "+f"(c[0]), "+f"(c[1]), "+f"(c[2]), "+f"(c[3])
        : "r"(a0), "r"(a1), "r"(a2), "r"(a3), "r"(b0), "r"(b1));
}

// ---------------- 1. A = F F^T + 0.5 I  ANALYTIC, band only ----------------
__global__ void k_buildA() {
    int bj = blockIdx.x, bi = bj + blockIdx.y;
    if (bi >= NBAS / 64) return;
    for (int t = threadIdx.x; t < 4096; t += 256) {
        int li = t >> 6, lj = t & 63;
        int i = bi * 64 + li, j = bj * 64 + lj;
        if (i < j) continue;
        double dmu = (double)((i >> 1) - (j >> 1)) * (1.0 / 511.0);
        double s2 = ((i & 1) ? 1e-4 : 2.5e-5) + ((j & 1) ? 1e-4 : 2.5e-5);
        double v = 512.0 * exp(-0.5 * dmu * dmu / s2) / sqrt(6.283185307179586 * s2);
        if (i == j) v += 0.5;
        g_A[(size_t)i * NBAS + j] = v;
    }
}

// ---------------- 1b. RHS = F[:, 256:768] ----------------
__global__ void k_buildFrhs() {
    int n = blockIdx.x;
    double mu = (double)(n >> 1) / 511.0;
    double sg = (n & 1) ? 0.01 : 0.005;
    double inv = 1.0 / (sg * 2.5066282746310002);
    for (int c = threadIdx.x; c < LM; c += blockDim.x) {
        double pos = 0.0009765625 + (double)c * (1.0 / 512.0);
        double z = (pos - mu) / sg;
        g_Frhs[n * LM + c] = exp(-0.5 * z * z) * inv;
    }
}

// ---------------- 2a. Cholesky diagonal block (64x64, fp64, div-free) ----------------
__global__ void k_chol_diag(int k0) {
    __shared__ double s[64][65];
    __shared__ double rs_sh;
    int tid = threadIdx.x;
    for (int t = tid; t < 4096; t += 256) {
        int i = t >> 6, j = t & 63;
        s[i][j] = (i >= j) ? g_A[(size_t)(k0 + i) * NBAS + k0 + j] : 0.0;
    }
    __syncthreads();
    for (int j = 0; j < 64; j++) {
        if (tid == 0) {
            double a = s[j][j];
            double r = (double)rsqrtf((float)a);
            r = r * (1.5 - 0.5 * a * r * r);   // Newton x2 -> full fp64 rsqrt
            r = r * (1.5 - 0.5 * a * r * r);
            rs_sh = r;
            s[j][j] = a * r;                    // sqrt(a)
        }
        __syncthreads();
        double r = rs_sh;
        for (int i = j + 1 + tid; i < 64; i += 256) s[i][j] *= r;
        __syncthreads();
        int rem = 63 - j;
        for (int t = tid; t < rem * rem; t += 256) {
            int i = j + 1 + t / rem, c = j + 1 + t % rem;
            if (c <= i) s[i][c] -= s[i][j] * s[c][j];
        }
        __syncthreads();
    }
    for (int t = tid; t < 4096; t += 256) {
        int i = t >> 6, j = t & 63;
        if (i >= j) g_A[(size_t)(k0 + i) * NBAS + k0 + j] = s[i][j];
    }
}

// ---------------- 2b. panel: L21 = A21 * L11^{-T}, div-free ----------------
__global__ void k_chol_panel(int k0) {
    __shared__ double Ld[64][64];
    __shared__ double dinv[64];
    int tid = threadIdx.x;
    for (int t = tid; t < 4096; t += 256) {
        int i = t >> 6, j = t & 63;
        Ld[i][j] = (i >= j) ? g_A[(size_t)(k0 + i) * NBAS + k0 + j] : 0.0;
    }
    __syncthreads();
    if (tid < 64) dinv[tid] = 1.0 / Ld[tid][tid];
    __syncthreads();
    int lane = tid & 31, w = tid >> 5;
    int row = k0 + 64 + blockIdx.x * 8 + w;
    if (row >= NBAS) return;
    double a0 = g_A[(size_t)row * NBAS + k0 + lane];
    double a1 = g_A[(size_t)row * NBAS + k0 + 32 + lane];
    for (int j = 0; j < 64; j++) {
        double p = 0.0;
        if (lane < j)       p += a0 * Ld[j][lane];
        if (lane + 32 < j)  p += a1 * Ld[j][lane + 32];
        p = wredd(p);
        double av = (j < 32) ? __shfl_sync(0xffffffffu, a0, j)
                             : __shfl_sync(0xffffffffu, a1, j - 32);
        double xj = (av - p) * dinv[j];
        if (j < 32) { if (lane == j) a0 = xj; }
        else        { if (lane == j - 32) a1 = xj; }
    }
    g_A[(size_t)row * NBAS + k0 + lane] = a0;
    g_A[(size_t)row * NBAS + k0 + 32 + lane] = a1;
}

// ---------------- 2c. trailing update (conflict-free staging) ----------------
__global__ void k_trail(int k0) {
    int pair = blockIdx.x >> 3, strip = blockIdx.x & 7;
    int dbi = (pair >= 1) ? 1 : 0, dbj = (pair == 2) ? 1 : 0;
    int i0 = k0 + 64 + dbi * 64 + strip * 8;
    int j0 = k0 + 64 + dbj * 64;
    if (i0 >= NBAS || j0 >= NBAS) return;
    __shared__ double LjT[64][65];   // LjT[k][c] = L[j0+c][k0+k]
    __shared__ double Li[8][65];
    int tid = threadIdx.x;
    for (int t = tid; t < 4096; t += 256) {
        int r = t >> 6, k = t & 63;
        LjT[k][r] = g_A[(size_t)(j0 + r) * NBAS + k0 + k];
    }
    for (int t = tid; t < 512; t += 256)
        Li[t >> 6][t & 63] = g_A[(size_t)(i0 + (t >> 6)) * NBAS + k0 + (t & 63)];
    __syncthreads();
    int r = tid >> 6, c = tid & 63;
    double acc0 = 0.0, acc1 = 0.0;
    #pragma unroll 8
    for (int k = 0; k < 64; k++) {
        double lj = LjT[k][c];
        acc0 += Li[r][k] * lj;
        acc1 += Li[r + 4][k] * lj;
    }
    g_A[(size_t)(i0 + r) * NBAS + j0 + c]     -= acc0;
    g_A[(size_t)(i0 + r + 4) * NBAS + j0 + c] -= acc1;
}

// ---------------- 2d. diagonal reciprocals for TRSM ----------------
__global__ void k_dinv() {
    int n = blockIdx.x * 256 + threadIdx.x;
    if (n < NBAS) g_dinv[n] = 1.0 / g_A[(size_t)n * NBAS + n];
}

// ---------------- 3. forward solve L Y = F_mid (band, div-free) ----------------
__global__ void __launch_bounds__(32) k_trsm_fwd() {
    __shared__ double ys[4][NBAS];
    int lane = threadIdx.x;
    int col0 = blockIdx.x * 4;
    for (int n = 0; n < NBAS; n++) {
        int jlo = ((n >> 6) >= 2) ? (((n >> 6) - 2) << 6) : 0;
        double a0 = 0, a1 = 0, a2 = 0, a3 = 0;
        const double* Ln = &g_A[(size_t)n * NBAS];
        for (int j = jlo + lane; j < n; j += 32) {
            double L = Ln[j];
            a0 += L * ys[0][j]; a1 += L * ys[1][j];
            a2 += L * ys[2][j]; a3 += L * ys[3][j];
        }
        a0 = wredd(a0); a1 = wredd(a1); a2 = wredd(a2); a3 = wredd(a3);
        double dinv = g_dinv[n];
        if (lane < 4) {
            double acc = (lane == 0) ? a0 : (lane == 1) ? a1 : (lane == 2) ? a2 : a3;
            double c = g_Frhs[n * LM + col0 + lane];
            double y = (c - acc) * dinv;
            ys[lane][n] = y;
            g_Yd[n * LM + col0 + lane] = y;
        }
        __syncwarp();
    }
}

// ---------------- 4. backward solve L^T X = Y (band, div-free) ----------------
__global__ void __launch_bounds__(32) k_trsm_bwd() {
    __shared__ double xs[4][NBAS];
    int lane = threadIdx.x;
    int col0 = blockIdx.x * 4;
    for (int n = NBAS - 1; n >= 0; n--) {
        int jhi = (((n >> 6) + 3) << 6); if (jhi > NBAS) jhi = NBAS;
        double a0 = 0, a1 = 0, a2 = 0, a3 = 0;
        for (int j = n + 1 + lane; j < jhi; j += 32) {
            double L = g_A[(size_t)j * NBAS + n];
            a0 += L * xs[0][j]; a1 += L * xs[1][j];
            a2 += L * xs[2][j]; a3 += L * xs[3][j];
        }
        a0 = wredd(a0); a1 = wredd(a1); a2 = wredd(a2); a3 = wredd(a3);
        double dinv = g_dinv[n];
        if (lane < 4) {
            double acc = (lane == 0) ? a0 : (lane == 1) ? a1 : (lane == 2) ? a2 : a3;
            double y = g_Yd[n * LM + col0 + lane];
            double x = (y - acc) * dinv;
            xs[lane][n] = x;
            g_X[n * LM + col0 + lane] = (float)x;
        }
        __syncwarp();
    }
}

// ---------------- double-buffered 128x128x16 SGEMM, C = A * op(B) ----------------
template <bool NT>
__global__ void __launch_bounds__(256) k_gemm(const float* __restrict__ Am,
                                              const float* __restrict__ Bm,
                                              float* __restrict__ C,
                                              int M, int Nn, int K) {
    __shared__ float As[2][16][132];
    __shared__ float Bs[2][16][132];
    int tid = threadIdx.x;
    int tx = tid & 15, ty = tid >> 4;
    int m0 = blockIdx.y * 128, n0 = blockIdx.x * 128;
    float4 av[2], bv[2];
    float acc[8][8] = {};
    int nk = K >> 4;

    #pragma unroll
    for (int i = 0; i < 2; i++) {
        int idx = tid + i * 256;
        av[i] = *(const float4*)&Am[(size_t)(m0 + (idx >> 2)) * K + (idx & 3) * 4];
        if (NT) bv[i] = *(const float4*)&Bm[(size_t)(n0 + (idx >> 2)) * K + (idx & 3) * 4];
        else    bv[i] = *(const float4*)&Bm[(size_t)(idx >> 5) * Nn + n0 + (idx & 31) * 4];
    }
    #pragma unroll
    for (int i = 0; i < 2; i++) {
        int idx = tid + i * 256;
        int r = idx >> 2, c = (idx & 3) * 4;
        As[0][c + 0][r] = av[i].x; As[0][c + 1][r] = av[i].y;
        As[0][c + 2][r] = av[i].z; As[0][c + 3][r] = av[i].w;
        if (NT) {
            Bs[0][c + 0][r] = bv[i].x; Bs[0][c + 1][r] = bv[i].y;
            Bs[0][c + 2][r] = bv[i].z; Bs[0][c + 3][r] = bv[i].w;
        } else {
            *(float4*)&Bs[0][idx >> 5][(idx & 31) * 4] = bv[i];
        }
    }
    __syncthreads();

    for (int s = 0; s < nk; s++) {
        if (s + 1 < nk) {
            int k0 = (s + 1) << 4;
            #pragma unroll
            for (int i = 0; i < 2; i++) {
                int idx = tid + i * 256;
                av[i] = *(const float4*)&Am[(size_t)(m0 + (idx >> 2)) * K + k0 + (idx & 3) * 4];
                if (NT) bv[i] = *(const float4*)&Bm[(size_t)(n0 + (idx >> 2)) * K + k0 + (idx & 3) * 4];
                else    bv[i] = *(const float4*)&Bm[(size_t)(k0 + (idx >> 5)) * Nn + n0 + (idx & 31) * 4];
            }
        }
        int b = s & 1;
        #pragma unroll
        for (int kk = 0; kk < 16; kk++) {
            float a[8], bb[8];
            *(float4*)&a[0]  = *(float4*)&As[b][kk][ty * 8];
            *(float4*)&a[4]  = *(float4*)&As[b][kk][ty * 8 + 4];
            *(float4*)&bb[0] = *(float4*)&Bs[b][kk][tx * 8];
            *(float4*)&bb[4] = *(float4*)&Bs[b][kk][tx * 8 + 4];
            #pragma unroll
            for (int i = 0; i < 8; i++)
                #pragma unroll
                for (int j = 0; j < 8; j++) acc[i][j] += a[i] * bb[j];
        }
        if (s + 1 < nk) {
            int nb = (s + 1) & 1;
            #pragma unroll
            for (int i = 0; i < 2; i++) {
                int idx = tid + i * 256;
                int r = idx >> 2, c = (idx & 3) * 4;
                As[nb][c + 0][r] = av[i].x; As[nb][c + 1][r] = av[i].y;
                As[nb][c + 2][r] = av[i].z; As[nb][c + 3][r] = av[i].w;
                if (NT) {
                    Bs[nb][c + 0][r] = bv[i].x; Bs[nb][c + 1][r] = bv[i].y;
                    Bs[nb][c + 2][r] = bv[i].z; Bs[nb][c + 3][r] = bv[i].w;
                } else {
                    *(float4*)&Bs[nb][idx >> 5][(idx & 31) * 4] = bv[i];
                }
            }
            __syncthreads();
        }
    }
    #pragma unroll
    for (int i = 0; i < 8; i++)
        #pragma unroll
        for (int j = 0; j < 8; j++)
            C[(size_t)(m0 + ty * 8 + i) * Nn + n0 + tx * 8 + j] = acc[i][j];
}

// ---------------- split fp32 -> bf16 hi/lo ----------------
__global__ void k_split(const float* __restrict__ in,
                        __nv_bfloat16* __restrict__ hi,
                        __nv_bfloat16* __restrict__ lo, int n4) {
    int i = blockIdx.x * 256 + threadIdx.x;
    if (i >= n4) return;
    float4 v = ((const float4*)in)[i];
    float vv[4] = {v.x, v.y, v.z, v.w};
    #pragma unroll
    for (int j = 0; j < 4; j++) {
        __nv_bfloat16 h = __float2bfloat16(vv[j]);
        hi[i * 4 + j] = h;
        lo[i * 4 + j] = __float2bfloat16(vv[j] - __bfloat162float(h));
    }
}

// ---------------- split-bf16 tensor-core NT GEMM: C = A * B^T ----------------
// A, B given as hi/lo bf16 row-major [rows][K]; K multiple of 32.
__global__ void __launch_bounds__(256) k_gemm_bf(
    const __nv_bfloat16* __restrict__ Ah, const __nv_bfloat16* __restrict__ Al,
    const __nv_bfloat16* __restrict__ Bh, const __nv_bfloat16* __restrict__ Bl,
    float* __restrict__ C, int M, int Nn, int K) {
    __shared__ __nv_bfloat16 sAh[128 * 40], sAl[128 * 40];
    __shared__ __nv_bfloat16 sBh[128 * 40], sBl[128 * 40];
    int tid = threadIdx.x, lane = tid & 31, wid = tid >> 5;
    int g = lane >> 2, tg = lane & 3;
    int wr = wid >> 1, wc = wid & 1;
    int m0b = blockIdx.y * 128, n0b = blockIdx.x * 128;
    const uint32_t* uAh = (const uint32_t*)sAh;
    const uint32_t* uAl = (const uint32_t*)sAl;
    const uint32_t* uBh = (const uint32_t*)sBh;
    const uint32_t* uBl = (const uint32_t*)sBl;
    float acc[2][8][4] = {};

    for (int k0 = 0; k0 < K; k0 += 32) {
        __syncthreads();
        #pragma unroll
        for (int i = 0; i < 2; i++) {
            int idx = tid + i * 256;
            int r = idx >> 2, c = (idx & 3) * 8;
            *(uint4*)&sAh[r * 40 + c] = *(const uint4*)&Ah[(size_t)(m0b + r) * K + k0 + c];
            *(uint4*)&sAl[r * 40 + c] = *(const uint4*)&Al[(size_t)(m0b + r) * K + k0 + c];
            *(uint4*)&sBh[r * 40 + c] = *(const uint4*)&Bh[(size_t)(n0b + r) * K + k0 + c];
            *(uint4*)&sBl[r * 40 + c] = *(const uint4*)&Bl[(size_t)(n0b + r) * K + k0 + c];
        }
        __syncthreads();
        #pragma unroll
        for (int kk = 0; kk < 2; kk++) {
            uint32_t ah[2][4], al[2][4];
            #pragma unroll
            for (int tm = 0; tm < 2; tm++) {
                int base = (wr * 32 + tm * 16 + g) * 20 + kk * 8 + tg;
                ah[tm][0] = uAh[base];
                ah[tm][1] = uAh[base + 8 * 20];
                ah[tm][2] = uAh[base + 4];
                ah[tm][3] = uAh[base + 8 * 20 + 4];
                al[tm][0] = uAl[base];
                al[tm][1] = uAl[base + 8 * 20];
                al[tm][2] = uAl[base + 4];
                al[tm][3] = uAl[base + 8 * 20 + 4];
            }
            #pragma unroll
            for (int tn = 0; tn < 8; tn++) {
                int bbase = (wc * 64 + tn * 8 + g) * 20 + kk * 8 + tg;
                uint32_t bh0 = uBh[bbase], bh1 = uBh[bbase + 4];
                uint32_t bl0 = uBl[bbase], bl1 = uBl[bbase + 4];
                #pragma unroll
                for (int tm = 0; tm < 2; tm++) {
                    mma16816(acc[tm][tn], ah[tm][0], ah[tm][1], ah[tm][2], ah[tm][3], bh0, bh1);
                    mma16816(acc[tm][tn], ah[tm][0], ah[tm][1], ah[tm][2], ah[tm][3], bl0, bl1);
                    mma16816(acc[tm][tn], al[tm][0], al[tm][1], al[tm][2], al[tm][3], bh0, bh1);
                }
            }
        }
    }
    #pragma unroll
    for (int tm = 0; tm < 2; tm++) {
        int mrow = m0b + wr * 32 + tm * 16 + g;
        #pragma unroll
        for (int tn = 0; tn < 8; tn++) {
            int ncol = n0b + wc * 64 + tn * 8 + tg * 2;
            C[(size_t)mrow * Nn + ncol]           = acc[tm][tn][0];
            C[(size_t)mrow * Nn + ncol + 1]       = acc[tm][tn][1];
            C[(size_t)(mrow + 8) * Nn + ncol]     = acc[tm][tn][2];
            C[(size_t)(mrow + 8) * Nn + ncol + 1] = acc[tm][tn][3];
        }
    }
}

// ---------------- 6. bwmu/bwsig = B^T w ----------------
__global__ void k_bw(const float* __restrict__ wmu, const float* __restrict__ wsig) {
    int d = blockIdx.x * 256 + threadIdx.x;
    float am = 0.f, as = 0.f;
    for (int n = 0; n < NBAS; n++) {
        float b = g_B[n * DM + d];
        am += wmu[n] * b;
        as += wsig[n] * b;
    }
    g_bw[d] = am;
    g_bw[DM + d] = as;
}

// ---------------- 7. kmu/ksig = W_key * bw ----------------
__global__ void k_kmat(const float* __restrict__ Wkey) {
    int lane = threadIdx.x & 31, w = threadIdx.x >> 5;
    int e = blockIdx.x * 8 + w;
    float am = 0.f, as = 0.f;
    const float* row = Wkey + (size_t)e * DM;
    for (int d = lane; d < DM; d += 32) {
        float wv = row[d];
        am += wv * g_bw[d];
        as += wv * g_bw[DM + d];
    }
    am = wredf(am); as = wredf(as);
    if (lane == 0) { g_kv[e] = am; g_kv[DM + e] = as; }
}

// ---------------- 8. mu_s / sigma_sq per (h,q) ----------------
__global__ void k_musig(const float* __restrict__ q) {
    int lane = threadIdx.x & 31, w = threadIdx.x >> 5;
    int row = blockIdx.x * 8 + w;          // h*QL + qq
    int h = row >> 11;
    const float* qp = q + (size_t)row * DD;
    float am = 0.f, as = 0.f;
    for (int dd = lane; dd < DD; dd += 32) {
        float v = qp[dd];
        am += v * g_kv[h * DD + dd];
        as += v * g_kv[DM + h * DD + dd];
    }
    am = wredf(am); as = wredf(as);
    if (lane == 0) {
        const float isq = 0.08838834764831845f;  // 1/sqrt(128)
        float xm = am * isq;
        float xs = as * isq;
        g_mu[row] = 1.0f / (1.0f + expf(-xm));
        float sp = fmaxf(xs, 0.f) + log1pf(expf(-fabsf(xs)));
        g_s2[row] = fmaxf(sp, 1e-4f);
    }
}

// ---------------- 9. fused r + context GEMM ----------------
__global__ void __launch_bounds__(256) k_context() {
    int h = blockIdx.y;
    int q0 = blockIdx.x * 64;
    __shared__ float rs[16][68];
    __shared__ float Vs[16][132];
    __shared__ float sm[64], sv[64];
    int tid = threadIdx.x, tx = tid & 15, ty = tid >> 4;
    if (tid < 64) {
        sm[tid] = g_mu[h * QL + q0 + tid];
        sv[tid] = g_s2[h * QL + q0 + tid];
    }
    __syncthreads();
    float acc[4][8] = {};
    for (int n0 = 0; n0 < NBAS; n0 += 16) {
        {
            int r = tid >> 4, c = (tid & 15) * 8;
            const float* src = &g_V[(size_t)(n0 + r) * DM + h * DD + c];
            *(float4*)&Vs[r][c]     = *(const float4*)&src[0];
            *(float4*)&Vs[r][c + 4] = *(const float4*)&src[4];
        }
        for (int t = tid; t < 1024; t += 256) {
            int nq = t & 63;
            int nn = t >> 6;
            int n = n0 + nn;
            float bmu = (float)(n >> 1) * (1.0f / 511.0f);
            float bs2 = (n & 1) ? 1e-4f : 2.5e-5f;
            float tt = sv[nq] + bs2;
            float rt = rsqrtf(tt);
            float df = bmu - sm[nq];
            rs[nn][nq] = __expf(-0.5f * df * df * rt * rt) * rt * 0.3989422804014327f;
        }
        __syncthreads();
        #pragma unroll
        for (int kk = 0; kk < 16; kk++) {
            float a[4], b[8];
            *(float4*)&a[0] = *(float4*)&rs[kk][ty * 4];
            *(float4*)&b[0] = *(float4*)&Vs[kk][tx * 8];
            *(float4*)&b[4] = *(float4*)&Vs[kk][tx * 8 + 4];
            #pragma unroll
            for (int i = 0; i < 4; i++)
                #pragma unroll
                for (int j = 0; j < 8; j++) acc[i][j] += a[i] * b[j];
        }
        __syncthreads();
    }
    #pragma unroll
    for (int i = 0; i < 4; i++)
        #pragma unroll
        for (int j = 0; j < 8; j++)
            g_ctx[(size_t)(q0 + ty * 4 + i) * DM + h * DD + tx * 8 + j] = acc[i][j];
}

// ---------------- host launcher ----------------
extern "C" void kernel_launch(void* const* d_in, const int* in_sizes, int n_in,
                              void* d_out, int out_size) {
    const float* k_in  = (const float*)d_in[0];   // (1, 512, 2048)
    const float* q_in  = (const float*)d_in[1];   // (1, 16, 2048, 128)
    const float* Wkey  = (const float*)d_in[2];   // (2048, 2048)
    const float* Wval  = (const float*)d_in[3];
    const float* Wout  = (const float*)d_in[4];
    const float* wmu   = (const float*)d_in[5];   // (1024,)
    const float* wsig  = (const float*)d_in[6];
    (void)n_in; (void)in_sizes; (void)out_size;

    float *pX, *pB, *pV, *pCtx;
    __nv_bfloat16 *pBh, *pBl, *pWvh, *pWvl, *pWoh, *pWol, *pCh, *pCl;
    cudaGetSymbolAddress((void**)&pX,   g_X);
    cudaGetSymbolAddress((void**)&pB,   g_B);
    cudaGetSymbolAddress((void**)&pV,   g_V);
    cudaGetSymbolAddress((void**)&pCtx, g_ctx);
    cudaGetSymbolAddress((void**)&pBh,  g_Bh);
    cudaGetSymbolAddress((void**)&pBl,  g_Bl);
    cudaGetSymbolAddress((void**)&pWvh, g_Wvh);
    cudaGetSymbolAddress((void**)&pWvl, g_Wvl);
    cudaGetSymbolAddress((void**)&pWoh, g_Woh);
    cudaGetSymbolAddress((void**)&pWol, g_Wol);
    cudaGetSymbolAddress((void**)&pCh,  g_Ch);
    cudaGetSymbolAddress((void**)&pCl,  g_Cl);

    // 0: split weight matrices (independent of solve chain)
    k_split<<<(DM * DM / 4 + 255) / 256, 256>>>(Wval, pWvh, pWvl, DM * DM / 4);
    k_split<<<(DM * DM / 4 + 255) / 256, 256>>>(Wout, pWoh, pWol, DM * DM / 4);

    // 1: analytic banded A and RHS
    k_buildA<<<dim3(16, 3), 256>>>();
    k_buildFrhs<<<NBAS, 256>>>();

    // 2: banded blocked Cholesky (fp64), block-band offset <= 2
    for (int k0 = 0; k0 < NBAS; k0 += 64) {
        k_chol_diag<<<1, 256>>>(k0);
        int rows = NBAS - k0 - 64;
        if (rows > 128) rows = 128;
        if (rows > 0) {
            k_chol_panel<<<rows / 8, 256>>>(k0);
            k_trail<<<24, 256>>>(k0);
        }
    }
    k_dinv<<<4, 256>>>();

    // 3-4: banded triangular solves -> X (fp32)
    k_trsm_fwd<<<128, 32>>>();
    k_trsm_bwd<<<128, 32>>>();

    // 5: B = X * k   (NN: X [1024][512], k [512][2048])
    k_gemm<false><<<dim3(DM / 128, NBAS / 128), 256>>>(pX, k_in, pB, NBAS, DM, LM);

    // 6-8: collapsed keys/scores path
    k_bw<<<DM / 256, 256>>>(wmu, wsig);
    k_kmat<<<DM / 8, 256>>>(Wkey);
    k_musig<<<(HH * QL) / 8, 256>>>(q_in);

    // 9: values = B * W_val^T (split-bf16 tensor cores)
    k_split<<<(NBAS * DM / 4 + 255) / 256, 256>>>(pB, pBh, pBl, NBAS * DM / 4);
    k_gemm_bf<<<dim3(DM / 128, NBAS / 128), 256>>>(pBh, pBl, pWvh, pWvl, pV, NBAS, DM, DM);

    // 10: fused r + context
    k_context<<<dim3(QL / 64, HH), 256>>>();

    // 11: out = ctx * W_out^T (split-bf16 tensor cores) -> d_out
    k_split<<<(QL * DM / 4 + 255) / 256, 256>>>(pCtx, pCh, pCl, QL * DM / 4);
    k_gemm_bf<<<dim3(DM / 128, QL / 128), 256>>>(pCh, pCl, pWoh, pWol, (float*)d_out, QL, DM, DM);
}